// round 1
// baseline (speedup 1.0000x reference)
#include <cuda_runtime.h>
#include <cuda_fp16.h>

// Problem constants (from reference)
#define IN_F   20000
#define OUT_F  3000
#define BATCH  8192
#define VB     4          // batch elems per thread in spmm
#define SPMM_T 256        // threads per spmm block -> 1024 batch per block

// Scratch (static __device__ globals; no runtime allocation)
__device__ __half g_xT[(size_t)IN_F * BATCH];   // 327 MB, x transposed to [col][batch], fp16
__device__ float  g_yT[(size_t)OUT_F * BATCH];  //  98 MB, y transposed [row][batch], fp32
__device__ int    g_rowptr[OUT_F + 1];

// ---------------------------------------------------------------------------
// 1) CSR row pointers: rows[] is sorted ascending (row-major flat indices),
//    so row_ptr[r] = lower_bound(rows, r).
// ---------------------------------------------------------------------------
__global__ void build_rowptr_kernel(const int* __restrict__ rows, int nnz) {
    int r = blockIdx.x * blockDim.x + threadIdx.x;
    if (r > OUT_F) return;
    int lo = 0, hi = nnz;
    while (lo < hi) {
        int mid = (lo + hi) >> 1;
        if (rows[mid] < r) lo = mid + 1; else hi = mid;
    }
    g_rowptr[r] = lo;
}

// ---------------------------------------------------------------------------
// 2) Transpose + convert: x[b][c] fp32 -> g_xT[c][b] fp16.  32x32 smem tiles.
//    IN_F % 32 == 0, BATCH % 32 == 0 -> no bounds checks.
// ---------------------------------------------------------------------------
__global__ void transpose_in_kernel(const float* __restrict__ x) {
    __shared__ float tile[32][33];
    const int c0 = blockIdx.x * 32;
    const int b0 = blockIdx.y * 32;
    #pragma unroll
    for (int i = 0; i < 32; i += 8) {
        int b = b0 + threadIdx.y + i;
        int c = c0 + threadIdx.x;
        tile[threadIdx.y + i][threadIdx.x] = x[(size_t)b * IN_F + c];
    }
    __syncthreads();
    #pragma unroll
    for (int i = 0; i < 32; i += 8) {
        int c = c0 + threadIdx.y + i;
        int b = b0 + threadIdx.x;
        g_xT[(size_t)c * BATCH + b] = __float2half(tile[threadIdx.x][threadIdx.y + i]);
    }
}

// ---------------------------------------------------------------------------
// 3) SpMM: block = (one output row r) x (1024-batch tile).
//    Stage (col, weight) chunks in SMEM; each thread accumulates VB=4 batch
//    elems in fp32 registers; xT load is one coalesced LDG.64 per nnz/thread.
//    grid = (OUT_F, BATCH / (SPMM_T*VB)); blockIdx.x fastest -> all rows of a
//    batch tile run together (40 MB working set, L2-resident).
// ---------------------------------------------------------------------------
__global__ void __launch_bounds__(SPMM_T) spmm_kernel(
    const int* __restrict__ cols, const float* __restrict__ wts)
{
    const int r  = blockIdx.x;
    const int b0 = blockIdx.y * (SPMM_T * VB);
    const int t  = threadIdx.x;

    const int start = g_rowptr[r];
    const int end   = g_rowptr[r + 1];

    __shared__ int   sc[SPMM_T];
    __shared__ float sw[SPMM_T];

    float a0 = 0.f, a1 = 0.f, a2 = 0.f, a3 = 0.f;
    const int boff = b0 + t * VB;

    for (int j0 = start; j0 < end; j0 += SPMM_T) {
        int j = j0 + t;
        if (j < end) { sc[t] = cols[j]; sw[t] = wts[j]; }
        __syncthreads();
        int n = min(SPMM_T, end - j0);
        #pragma unroll 4
        for (int k = 0; k < n; k++) {
            int   c = sc[k];
            float w = sw[k];
            const uint2 v = *reinterpret_cast<const uint2*>(
                &g_xT[(size_t)c * BATCH + boff]);
            half2 h01 = *reinterpret_cast<const half2*>(&v.x);
            half2 h23 = *reinterpret_cast<const half2*>(&v.y);
            float2 f01 = __half22float2(h01);
            float2 f23 = __half22float2(h23);
            a0 = fmaf(w, f01.x, a0);
            a1 = fmaf(w, f01.y, a1);
            a2 = fmaf(w, f23.x, a2);
            a3 = fmaf(w, f23.y, a3);
        }
        __syncthreads();
    }

    float4 o = make_float4(a0, a1, a2, a3);
    *reinterpret_cast<float4*>(&g_yT[(size_t)r * BATCH + boff]) = o;
}

// ---------------------------------------------------------------------------
// 4) Transpose-out + bias: g_yT[r][b] -> out[b][r] + bias[r].
// ---------------------------------------------------------------------------
__global__ void transpose_out_kernel(const float* __restrict__ bias,
                                     float* __restrict__ out)
{
    __shared__ float tile[32][33];
    const int r0 = blockIdx.x * 32;
    const int b0 = blockIdx.y * 32;
    #pragma unroll
    for (int i = 0; i < 32; i += 8) {
        int r = r0 + threadIdx.y + i;
        int b = b0 + threadIdx.x;
        float v = 0.f;
        if (r < OUT_F) v = g_yT[(size_t)r * BATCH + b];
        tile[threadIdx.y + i][threadIdx.x] = v;
    }
    __syncthreads();
    #pragma unroll
    for (int i = 0; i < 32; i += 8) {
        int b = b0 + threadIdx.y + i;
        int r = r0 + threadIdx.x;
        if (r < OUT_F)
            out[(size_t)b * OUT_F + r] = tile[threadIdx.x][threadIdx.y + i] + bias[r];
    }
}

// ---------------------------------------------------------------------------
// Launch. Inputs (metadata order): inputs f32 [8192*20000], weights f32 [nnz],
// bias f32 [3000], rows i32 [nnz], cols i32 [nnz]. Output f32 [8192*3000].
// ---------------------------------------------------------------------------
extern "C" void kernel_launch(void* const* d_in, const int* in_sizes, int n_in,
                              void* d_out, int out_size)
{
    const float* x    = (const float*)d_in[0];
    const float* wts  = (const float*)d_in[1];
    const float* bias = (const float*)d_in[2];
    const int*   rows = (const int*)  d_in[3];
    const int*   cols = (const int*)  d_in[4];
    const int    nnz  = in_sizes[1];
    float* out = (float*)d_out;

    build_rowptr_kernel<<<(OUT_F + 1 + 255) / 256, 256>>>(rows, nnz);
    transpose_in_kernel<<<dim3(IN_F / 32, BATCH / 32), dim3(32, 8)>>>(x);
    spmm_kernel<<<dim3(OUT_F, BATCH / (SPMM_T * VB)), SPMM_T>>>(cols, wts);
    transpose_out_kernel<<<dim3((OUT_F + 31) / 32, BATCH / 32), dim3(32, 8)>>>(bias, out);
}

// round 2
// speedup vs baseline: 1.0475x; 1.0475x over previous
#include <cuda_runtime.h>
#include <cuda_fp16.h>

// Problem constants (from reference)
#define IN_F   20000
#define OUT_F  3000
#define BATCH  8192
#define VB     4          // batch elems per thread in spmm
#define SPMM_T 256        // threads per spmm block -> 1024 batch per block

// Scratch (static __device__ globals; no runtime allocation)
__device__ __half g_xT[(size_t)IN_F * BATCH];   // 327 MB, x transposed to [col][batch], fp16
__device__ float  g_yT[(size_t)OUT_F * BATCH];  //  98 MB, y transposed [row][batch], fp32
__device__ int    g_rowptr[OUT_F + 1];

// ---------------------------------------------------------------------------
// 1) CSR row pointers: rows[] sorted ascending -> row_ptr[r] = lower_bound.
// ---------------------------------------------------------------------------
__global__ void build_rowptr_kernel(const int* __restrict__ rows, int nnz) {
    int r = blockIdx.x * blockDim.x + threadIdx.x;
    if (r > OUT_F) return;
    int lo = 0, hi = nnz;
    while (lo < hi) {
        int mid = (lo + hi) >> 1;
        if (rows[mid] < r) lo = mid + 1; else hi = mid;
    }
    g_rowptr[r] = lo;
}

// ---------------------------------------------------------------------------
// 2) Transpose + convert: x[b][c] fp32 -> g_xT[c][b] fp16.
//    Tile: 32 cols x 64 batch, 256 threads.
//    Load : float4 per thread (2 iters), 128B-per-16-lane-row, full lines.
//    Store: 16B (8 halfs) per thread -> 128B contiguous per column row.
//    SMEM tile[c][b] with row stride 65 floats -> load-phase conflict-free.
// ---------------------------------------------------------------------------
__global__ void __launch_bounds__(256) transpose_in_kernel(const float* __restrict__ x) {
    __shared__ __align__(16) float tile[32][65];   // [c][b], pad 1
    const int c0 = blockIdx.x * 32;
    const int b0 = blockIdx.y * 64;
    const int t  = threadIdx.x;

    // Load phase: tx = c-group (0..7, 4 cols each), ty = b-row (0..31), 2 iters
    const int tx = t & 7;
    const int ty = t >> 3;
    #pragma unroll
    for (int i = 0; i < 2; i++) {
        const int bl = ty + 32 * i;
        const float4 v = *reinterpret_cast<const float4*>(
            &x[(size_t)(b0 + bl) * IN_F + c0 + tx * 4]);
        tile[tx * 4 + 0][bl] = v.x;
        tile[tx * 4 + 1][bl] = v.y;
        tile[tx * 4 + 2][bl] = v.z;
        tile[tx * 4 + 3][bl] = v.w;
    }
    __syncthreads();

    // Store phase: c = t>>3 (0..31), bg = (t&7)*8 -> 8 halfs = 16B per thread
    const int c  = t >> 3;
    const int bg = (t & 7) * 8;
    __half h[8];
    #pragma unroll
    for (int i = 0; i < 8; i++) h[i] = __float2half(tile[c][bg + i]);
    *reinterpret_cast<uint4*>(&g_xT[(size_t)(c0 + c) * BATCH + b0 + bg]) =
        *reinterpret_cast<const uint4*>(h);
}

// ---------------------------------------------------------------------------
// 3) SpMM: block = (one output row r) x (1024-batch tile). Unchanged from R1:
//    this kernel runs at the chip LTS cap (9.8 GB of L2 reads is the floor).
// ---------------------------------------------------------------------------
__global__ void __launch_bounds__(SPMM_T) spmm_kernel(
    const int* __restrict__ cols, const float* __restrict__ wts)
{
    const int r  = blockIdx.x;
    const int b0 = blockIdx.y * (SPMM_T * VB);
    const int t  = threadIdx.x;

    const int start = g_rowptr[r];
    const int end   = g_rowptr[r + 1];

    __shared__ int   sc[SPMM_T];
    __shared__ float sw[SPMM_T];

    float a0 = 0.f, a1 = 0.f, a2 = 0.f, a3 = 0.f;
    const int boff = b0 + t * VB;

    for (int j0 = start; j0 < end; j0 += SPMM_T) {
        int j = j0 + t;
        if (j < end) { sc[t] = cols[j]; sw[t] = wts[j]; }
        __syncthreads();
        int n = min(SPMM_T, end - j0);
        #pragma unroll 4
        for (int k = 0; k < n; k++) {
            int   c = sc[k];
            float w = sw[k];
            const uint2 v = *reinterpret_cast<const uint2*>(
                &g_xT[(size_t)c * BATCH + boff]);
            half2 h01 = *reinterpret_cast<const half2*>(&v.x);
            half2 h23 = *reinterpret_cast<const half2*>(&v.y);
            float2 f01 = __half22float2(h01);
            float2 f23 = __half22float2(h23);
            a0 = fmaf(w, f01.x, a0);
            a1 = fmaf(w, f01.y, a1);
            a2 = fmaf(w, f23.x, a2);
            a3 = fmaf(w, f23.y, a3);
        }
        __syncthreads();
    }

    float4 o = make_float4(a0, a1, a2, a3);
    *reinterpret_cast<float4*>(&g_yT[(size_t)r * BATCH + boff]) = o;
}

// ---------------------------------------------------------------------------
// 4) Transpose-out + bias: g_yT[r][b] -> out[b][r] + bias[r].
//    Tile: 32 rows x 64 batch, 256 threads, float4 on both global sides.
// ---------------------------------------------------------------------------
__global__ void __launch_bounds__(256) transpose_out_kernel(
    const float* __restrict__ bias, float* __restrict__ out)
{
    __shared__ __align__(16) float tile[32][65];   // [r][b], pad 1
    const int r0 = blockIdx.x * 32;
    const int b0 = blockIdx.y * 64;
    const int t  = threadIdx.x;

    // Load phase: yT[r][b0..b0+63]: tx = b-float4 (0..15), ty = r (0..15), 2 iters
    const int tx = t & 15;
    const int ty = t >> 4;
    #pragma unroll
    for (int i = 0; i < 2; i++) {
        const int rl = ty + 16 * i;
        const int r  = r0 + rl;
        float4 v = make_float4(0.f, 0.f, 0.f, 0.f);
        if (r < OUT_F)
            v = *reinterpret_cast<const float4*>(
                &g_yT[(size_t)r * BATCH + b0 + tx * 4]);
        tile[rl][tx * 4 + 0] = v.x;
        tile[rl][tx * 4 + 1] = v.y;
        tile[rl][tx * 4 + 2] = v.z;
        tile[rl][tx * 4 + 3] = v.w;
    }
    __syncthreads();

    // Store phase: bb = t>>3 (0..31, +32 second iter), rr = (t&7)*4
    const int bb = t >> 3;
    const int rr = (t & 7) * 4;
    const int rg = r0 + rr;

    float bz = 0.f, by = 0.f, bx = 0.f, bw = 0.f;
    if (rg + 0 < OUT_F) bx = bias[rg + 0];
    if (rg + 1 < OUT_F) by = bias[rg + 1];
    if (rg + 2 < OUT_F) bz = bias[rg + 2];
    if (rg + 3 < OUT_F) bw = bias[rg + 3];

    #pragma unroll
    for (int i = 0; i < 2; i++) {
        const int b = b0 + bb + 32 * i;
        float4 o;
        o.x = tile[rr + 0][bb + 32 * i] + bx;
        o.y = tile[rr + 1][bb + 32 * i] + by;
        o.z = tile[rr + 2][bb + 32 * i] + bz;
        o.w = tile[rr + 3][bb + 32 * i] + bw;
        if (rg + 3 < OUT_F) {
            *reinterpret_cast<float4*>(&out[(size_t)b * OUT_F + rg]) = o;
        } else {
            if (rg + 0 < OUT_F) out[(size_t)b * OUT_F + rg + 0] = o.x;
            if (rg + 1 < OUT_F) out[(size_t)b * OUT_F + rg + 1] = o.y;
            if (rg + 2 < OUT_F) out[(size_t)b * OUT_F + rg + 2] = o.z;
            if (rg + 3 < OUT_F) out[(size_t)b * OUT_F + rg + 3] = o.w;
        }
    }
}

// ---------------------------------------------------------------------------
// Launch. Inputs (metadata order): inputs f32 [8192*20000], weights f32 [nnz],
// bias f32 [3000], rows i32 [nnz], cols i32 [nnz]. Output f32 [8192*3000].
// ---------------------------------------------------------------------------
extern "C" void kernel_launch(void* const* d_in, const int* in_sizes, int n_in,
                              void* d_out, int out_size)
{
    const float* x    = (const float*)d_in[0];
    const float* wts  = (const float*)d_in[1];
    const float* bias = (const float*)d_in[2];
    const int*   rows = (const int*)  d_in[3];
    const int*   cols = (const int*)  d_in[4];
    const int    nnz  = in_sizes[1];
    float* out = (float*)d_out;

    build_rowptr_kernel<<<(OUT_F + 1 + 255) / 256, 256>>>(rows, nnz);
    transpose_in_kernel<<<dim3(IN_F / 32, BATCH / 64), 256>>>(x);
    spmm_kernel<<<dim3(OUT_F, BATCH / (SPMM_T * VB)), SPMM_T>>>(cols, wts);
    transpose_out_kernel<<<dim3((OUT_F + 31) / 32, BATCH / 64), 256>>>(bias, out);
}

// round 4
// speedup vs baseline: 1.2196x; 1.1643x over previous
#include <cuda_runtime.h>
#include <cuda_fp16.h>

// Problem constants (from reference)
#define IN_F   20000
#define OUT_F  3000
#define BATCH  8192
#define VB     8          // batch elems per thread in spmm
#define SPMM_T 128        // threads per spmm block -> 1024 batch per block

// Scratch (static __device__ globals; no runtime allocation)
__device__ __half g_xT[(size_t)IN_F * BATCH];   // 327 MB, x transposed to [col][batch], fp16
__device__ float  g_yT[(size_t)OUT_F * BATCH];  //  98 MB, y transposed [row][batch], fp32
__device__ int    g_rowptr[OUT_F + 1];

// ---------------------------------------------------------------------------
// 1) CSR row pointers: rows[] sorted ascending -> row_ptr[r] = lower_bound.
// ---------------------------------------------------------------------------
__global__ void build_rowptr_kernel(const int* __restrict__ rows, int nnz) {
    int r = blockIdx.x * blockDim.x + threadIdx.x;
    if (r > OUT_F) return;
    int lo = 0, hi = nnz;
    while (lo < hi) {
        int mid = (lo + hi) >> 1;
        if (rows[mid] < r) lo = mid + 1; else hi = mid;
    }
    g_rowptr[r] = lo;
}

// ---------------------------------------------------------------------------
// 2) Transpose + convert: x[b][c] fp32 -> g_xT[c][b] fp16.
//    Tile: 32 cols x 64 batch, 256 threads. float4 loads, 16B fp16 stores.
// ---------------------------------------------------------------------------
__global__ void __launch_bounds__(256) transpose_in_kernel(const float* __restrict__ x) {
    __shared__ __align__(16) float tile[32][65];   // [c][b], pad 1
    const int c0 = blockIdx.x * 32;
    const int b0 = blockIdx.y * 64;
    const int t  = threadIdx.x;

    const int tx = t & 7;
    const int ty = t >> 3;
    #pragma unroll
    for (int i = 0; i < 2; i++) {
        const int bl = ty + 32 * i;
        const float4 v = *reinterpret_cast<const float4*>(
            &x[(size_t)(b0 + bl) * IN_F + c0 + tx * 4]);
        tile[tx * 4 + 0][bl] = v.x;
        tile[tx * 4 + 1][bl] = v.y;
        tile[tx * 4 + 2][bl] = v.z;
        tile[tx * 4 + 3][bl] = v.w;
    }
    __syncthreads();

    const int c  = t >> 3;
    const int bg = (t & 7) * 8;
    __half h[8];
    #pragma unroll
    for (int i = 0; i < 8; i++) h[i] = __float2half(tile[c][bg + i]);
    *reinterpret_cast<uint4*>(&g_xT[(size_t)(c0 + c) * BATCH + b0 + bg]) =
        *reinterpret_cast<const uint4*>(h);
}

// ---------------------------------------------------------------------------
// 3) SpMM: block = (one output row r) x (1024-batch tile).
//    VB=8: one LDG.128 of xT per 8 (nnz,batch) pairs; metadata packed as
//    int2 in SMEM -> one LDS.64 broadcast per nnz. Issue-count minimized.
// ---------------------------------------------------------------------------
__global__ void __launch_bounds__(SPMM_T) spmm_kernel(
    const int* __restrict__ cols, const float* __restrict__ wts)
{
    const int r  = blockIdx.x;
    const int b0 = blockIdx.y * (SPMM_T * VB);
    const int t  = threadIdx.x;

    const int start = g_rowptr[r];
    const int end   = g_rowptr[r + 1];

    __shared__ __align__(8) int2 spk[SPMM_T];     // {col, w bits}

    float a0 = 0.f, a1 = 0.f, a2 = 0.f, a3 = 0.f;
    float a4 = 0.f, a5 = 0.f, a6 = 0.f, a7 = 0.f;
    const int boff = b0 + t * VB;
    const __half* __restrict__ xT = g_xT;

    for (int j0 = start; j0 < end; j0 += SPMM_T) {
        int j = j0 + t;
        if (j < end) {
            int2 p;
            p.x = cols[j];
            p.y = __float_as_int(wts[j]);
            spk[t] = p;
        }
        __syncthreads();
        int n = min(SPMM_T, end - j0);
        #pragma unroll 4
        for (int k = 0; k < n; k++) {
            const int2  p = spk[k];
            const float w = __int_as_float(p.y);
            const uint4 v = *reinterpret_cast<const uint4*>(
                &xT[(size_t)p.x * BATCH + boff]);
            const half2 h0 = *reinterpret_cast<const half2*>(&v.x);
            const half2 h1 = *reinterpret_cast<const half2*>(&v.y);
            const half2 h2 = *reinterpret_cast<const half2*>(&v.z);
            const half2 h3 = *reinterpret_cast<const half2*>(&v.w);
            const float2 f0 = __half22float2(h0);
            const float2 f1 = __half22float2(h1);
            const float2 f2 = __half22float2(h2);
            const float2 f3 = __half22float2(h3);
            a0 = fmaf(w, f0.x, a0);  a1 = fmaf(w, f0.y, a1);
            a2 = fmaf(w, f1.x, a2);  a3 = fmaf(w, f1.y, a3);
            a4 = fmaf(w, f2.x, a4);  a5 = fmaf(w, f2.y, a5);
            a6 = fmaf(w, f3.x, a6);  a7 = fmaf(w, f3.y, a7);
        }
        __syncthreads();
    }

    float* yp = &g_yT[(size_t)r * BATCH + boff];
    *reinterpret_cast<float4*>(yp)     = make_float4(a0, a1, a2, a3);
    *reinterpret_cast<float4*>(yp + 4) = make_float4(a4, a5, a6, a7);
}

// ---------------------------------------------------------------------------
// 4) Transpose-out + bias: g_yT[r][b] -> out[b][r] + bias[r].
// ---------------------------------------------------------------------------
__global__ void __launch_bounds__(256) transpose_out_kernel(
    const float* __restrict__ bias, float* __restrict__ out)
{
    __shared__ __align__(16) float tile[32][65];   // [r][b], pad 1
    const int r0 = blockIdx.x * 32;
    const int b0 = blockIdx.y * 64;
    const int t  = threadIdx.x;

    const int tx = t & 15;
    const int ty = t >> 4;
    #pragma unroll
    for (int i = 0; i < 2; i++) {
        const int rl = ty + 16 * i;
        const int r  = r0 + rl;
        float4 v = make_float4(0.f, 0.f, 0.f, 0.f);
        if (r < OUT_F)
            v = *reinterpret_cast<const float4*>(
                &g_yT[(size_t)r * BATCH + b0 + tx * 4]);
        tile[rl][tx * 4 + 0] = v.x;
        tile[rl][tx * 4 + 1] = v.y;
        tile[rl][tx * 4 + 2] = v.z;
        tile[rl][tx * 4 + 3] = v.w;
    }
    __syncthreads();

    const int bb = t >> 3;
    const int rr = (t & 7) * 4;
    const int rg = r0 + rr;

    float bx = 0.f, by = 0.f, bz = 0.f, bw = 0.f;
    if (rg + 0 < OUT_F) bx = bias[rg + 0];
    if (rg + 1 < OUT_F) by = bias[rg + 1];
    if (rg + 2 < OUT_F) bz = bias[rg + 2];
    if (rg + 3 < OUT_F) bw = bias[rg + 3];

    #pragma unroll
    for (int i = 0; i < 2; i++) {
        const int b = b0 + bb + 32 * i;
        float4 o;
        o.x = tile[rr + 0][bb + 32 * i] + bx;
        o.y = tile[rr + 1][bb + 32 * i] + by;
        o.z = tile[rr + 2][bb + 32 * i] + bz;
        o.w = tile[rr + 3][bb + 32 * i] + bw;
        if (rg + 3 < OUT_F) {
            *reinterpret_cast<float4*>(&out[(size_t)b * OUT_F + rg]) = o;
        } else {
            if (rg + 0 < OUT_F) out[(size_t)b * OUT_F + rg + 0] = o.x;
            if (rg + 1 < OUT_F) out[(size_t)b * OUT_F + rg + 1] = o.y;
            if (rg + 2 < OUT_F) out[(size_t)b * OUT_F + rg + 2] = o.z;
            if (rg + 3 < OUT_F) out[(size_t)b * OUT_F + rg + 3] = o.w;
        }
    }
}

// ---------------------------------------------------------------------------
// Launch. Inputs (metadata order): inputs f32 [8192*20000], weights f32 [nnz],
// bias f32 [3000], rows i32 [nnz], cols i32 [nnz]. Output f32 [8192*3000].
// ---------------------------------------------------------------------------
extern "C" void kernel_launch(void* const* d_in, const int* in_sizes, int n_in,
                              void* d_out, int out_size)
{
    const float* x    = (const float*)d_in[0];
    const float* wts  = (const float*)d_in[1];
    const float* bias = (const float*)d_in[2];
    const int*   rows = (const int*)  d_in[3];
    const int*   cols = (const int*)  d_in[4];
    const int    nnz  = in_sizes[1];
    float* out = (float*)d_out;

    build_rowptr_kernel<<<(OUT_F + 1 + 255) / 256, 256>>>(rows, nnz);
    transpose_in_kernel<<<dim3(IN_F / 32, BATCH / 64), 256>>>(x);
    spmm_kernel<<<dim3(OUT_F, BATCH / (SPMM_T * VB)), SPMM_T>>>(cols, wts);
    transpose_out_kernel<<<dim3((OUT_F + 31) / 32, BATCH / 64), 256>>>(bias, out);
}

// round 6
// speedup vs baseline: 1.2197x; 1.0001x over previous
#include <cuda_runtime.h>
#include <cuda_fp16.h>

// Problem constants (from reference)
#define IN_F   20000
#define OUT_F  3000
#define BATCH  8192
#define VB     8          // batch elems per thread in spmm
#define SPMM_T 128        // threads per spmm block -> 1024 batch per block

// Scratch (static __device__ globals; no runtime allocation)
__device__ __half g_xT[(size_t)IN_F * BATCH];   // 327 MB, x transposed to [col][batch], fp16
__device__ float  g_yT[(size_t)OUT_F * BATCH];  //  98 MB, y transposed [row][batch], fp32
__device__ int    g_rowptr[OUT_F + 1];

// ---------------------------------------------------------------------------
// 1) CSR row pointers: rows[] sorted ascending -> row_ptr[r] = lower_bound.
// ---------------------------------------------------------------------------
__global__ void build_rowptr_kernel(const int* __restrict__ rows, int nnz) {
    int r = blockIdx.x * blockDim.x + threadIdx.x;
    if (r > OUT_F) return;
    int lo = 0, hi = nnz;
    while (lo < hi) {
        int mid = (lo + hi) >> 1;
        if (rows[mid] < r) lo = mid + 1; else hi = mid;
    }
    g_rowptr[r] = lo;
}

// ---------------------------------------------------------------------------
// 2) Transpose + convert: x[b][c] fp32 -> g_xT[c][b] fp16.  (unchanged)
// ---------------------------------------------------------------------------
__global__ void __launch_bounds__(256) transpose_in_kernel(const float* __restrict__ x) {
    __shared__ __align__(16) float tile[32][65];   // [c][b], pad 1
    const int c0 = blockIdx.x * 32;
    const int b0 = blockIdx.y * 64;
    const int t  = threadIdx.x;

    const int tx = t & 7;
    const int ty = t >> 3;
    #pragma unroll
    for (int i = 0; i < 2; i++) {
        const int bl = ty + 32 * i;
        const float4 v = *reinterpret_cast<const float4*>(
            &x[(size_t)(b0 + bl) * IN_F + c0 + tx * 4]);
        tile[tx * 4 + 0][bl] = v.x;
        tile[tx * 4 + 1][bl] = v.y;
        tile[tx * 4 + 2][bl] = v.z;
        tile[tx * 4 + 3][bl] = v.w;
    }
    __syncthreads();

    const int c  = t >> 3;
    const int bg = (t & 7) * 8;
    __half h[8];
    #pragma unroll
    for (int i = 0; i < 8; i++) h[i] = __float2half(tile[c][bg + i]);
    *reinterpret_cast<uint4*>(&g_xT[(size_t)(c0 + c) * BATCH + b0 + bg]) =
        *reinterpret_cast<const uint4*>(h);
}

// ---------------------------------------------------------------------------
// Packed helpers: half2 -> f32x2 (64-bit pair) and fma.rn.f32x2 (FFMA2).
// ---------------------------------------------------------------------------
__device__ __forceinline__ unsigned long long h2_to_f32x2(unsigned int h2) {
    unsigned long long r;
    asm("{\n\t"
        ".reg .f16 lo, hi;\n\t"
        ".reg .f32 a, b;\n\t"
        "mov.b32 {lo, hi}, %1;\n\t"
        "cvt.f32.f16 a, lo;\n\t"
        "cvt.f32.f16 b, hi;\n\t"
        "mov.b64 %0, {a, b};\n\t"
        "}" : "=l"(r) : "r"(h2));
    return r;
}

__device__ __forceinline__ void ffma2(unsigned long long& acc,
                                      unsigned long long xv,
                                      unsigned long long w2) {
    asm("fma.rn.f32x2 %0, %1, %2, %0;" : "+l"(acc) : "l"(xv), "l"(w2));
}

__device__ __forceinline__ unsigned long long bcast_f32x2(float w) {
    unsigned long long r;
    asm("mov.b64 %0, {%1, %1};" : "=l"(r) : "f"(w));
    return r;
}

__device__ __forceinline__ float2 unpack_f32x2(unsigned long long p) {
    float2 f;
    asm("mov.b64 {%0, %1}, %2;" : "=f"(f.x), "=f"(f.y) : "l"(p));
    return f;
}

// ---------------------------------------------------------------------------
// 3) SpMM: block = (one output row r) x (1024-batch tile).
//    2 nnz per inner iter: 1 LDS.128 metadata + 2 LDG.128 x + 8 FFMA2.
// ---------------------------------------------------------------------------
__global__ void __launch_bounds__(SPMM_T) spmm_kernel(
    const int* __restrict__ cols, const float* __restrict__ wts)
{
    const int r  = blockIdx.x;
    const int b0 = blockIdx.y * (SPMM_T * VB);
    const int t  = threadIdx.x;

    const int start = g_rowptr[r];
    const int end   = g_rowptr[r + 1];

    __shared__ __align__(16) int2 spk[SPMM_T + 2];   // {col, w bits}, +pad for dummy

    unsigned long long acc0 = 0ull, acc1 = 0ull, acc2 = 0ull, acc3 = 0ull;
    const int boff = b0 + t * VB;
    const __half* __restrict__ xT = g_xT;

    for (int j0 = start; j0 < end; j0 += SPMM_T) {
        const int n = min(SPMM_T, end - j0);
        int j = j0 + t;
        if (j < end) {
            int2 p;
            p.x = cols[j];
            p.y = __float_as_int(wts[j]);
            spk[t] = p;
        }
        if (t == 0 && (n & 1)) spk[n] = make_int2(0, 0);  // zero-weight dummy
        __syncthreads();
        const int n2 = (n + 1) & ~1;
        #pragma unroll 2
        for (int k = 0; k < n2; k += 2) {
            const int4 pp = *reinterpret_cast<const int4*>(&spk[k]);
            // nnz A
            {
                const unsigned long long w2 = bcast_f32x2(__int_as_float(pp.y));
                const uint4 v = *reinterpret_cast<const uint4*>(
                    &xT[(size_t)pp.x * BATCH + boff]);
                ffma2(acc0, h2_to_f32x2(v.x), w2);
                ffma2(acc1, h2_to_f32x2(v.y), w2);
                ffma2(acc2, h2_to_f32x2(v.z), w2);
                ffma2(acc3, h2_to_f32x2(v.w), w2);
            }
            // nnz B
            {
                const unsigned long long w2 = bcast_f32x2(__int_as_float(pp.w));
                const uint4 v = *reinterpret_cast<const uint4*>(
                    &xT[(size_t)pp.z * BATCH + boff]);
                ffma2(acc0, h2_to_f32x2(v.x), w2);
                ffma2(acc1, h2_to_f32x2(v.y), w2);
                ffma2(acc2, h2_to_f32x2(v.z), w2);
                ffma2(acc3, h2_to_f32x2(v.w), w2);
            }
        }
        __syncthreads();
    }

    const float2 f0 = unpack_f32x2(acc0);
    const float2 f1 = unpack_f32x2(acc1);
    const float2 f2 = unpack_f32x2(acc2);
    const float2 f3 = unpack_f32x2(acc3);
    float* yp = &g_yT[(size_t)r * BATCH + boff];
    *reinterpret_cast<float4*>(yp)     = make_float4(f0.x, f0.y, f1.x, f1.y);
    *reinterpret_cast<float4*>(yp + 4) = make_float4(f2.x, f2.y, f3.x, f3.y);
}

// ---------------------------------------------------------------------------
// 4) Transpose-out + bias: g_yT[r][b] -> out[b][r] + bias[r].  (unchanged)
// ---------------------------------------------------------------------------
__global__ void __launch_bounds__(256) transpose_out_kernel(
    const float* __restrict__ bias, float* __restrict__ out)
{
    __shared__ __align__(16) float tile[32][65];   // [r][b], pad 1
    const int r0 = blockIdx.x * 32;
    const int b0 = blockIdx.y * 64;
    const int t  = threadIdx.x;

    const int tx = t & 15;
    const int ty = t >> 4;
    #pragma unroll
    for (int i = 0; i < 2; i++) {
        const int rl = ty + 16 * i;
        const int r  = r0 + rl;
        float4 v = make_float4(0.f, 0.f, 0.f, 0.f);
        if (r < OUT_F)
            v = *reinterpret_cast<const float4*>(
                &g_yT[(size_t)r * BATCH + b0 + tx * 4]);
        tile[rl][tx * 4 + 0] = v.x;
        tile[rl][tx * 4 + 1] = v.y;
        tile[rl][tx * 4 + 2] = v.z;
        tile[rl][tx * 4 + 3] = v.w;
    }
    __syncthreads();

    const int bb = t >> 3;
    const int rr = (t & 7) * 4;
    const int rg = r0 + rr;

    float bx = 0.f, by = 0.f, bz = 0.f, bw = 0.f;
    if (rg + 0 < OUT_F) bx = bias[rg + 0];
    if (rg + 1 < OUT_F) by = bias[rg + 1];
    if (rg + 2 < OUT_F) bz = bias[rg + 2];
    if (rg + 3 < OUT_F) bw = bias[rg + 3];

    #pragma unroll
    for (int i = 0; i < 2; i++) {
        const int b = b0 + bb + 32 * i;
        float4 o;
        o.x = tile[rr + 0][bb + 32 * i] + bx;
        o.y = tile[rr + 1][bb + 32 * i] + by;
        o.z = tile[rr + 2][bb + 32 * i] + bz;
        o.w = tile[rr + 3][bb + 32 * i] + bw;
        if (rg + 3 < OUT_F) {
            *reinterpret_cast<float4*>(&out[(size_t)b * OUT_F + rg]) = o;
        } else {
            if (rg + 0 < OUT_F) out[(size_t)b * OUT_F + rg + 0] = o.x;
            if (rg + 1 < OUT_F) out[(size_t)b * OUT_F + rg + 1] = o.y;
            if (rg + 2 < OUT_F) out[(size_t)b * OUT_F + rg + 2] = o.z;
            if (rg + 3 < OUT_F) out[(size_t)b * OUT_F + rg + 3] = o.w;
        }
    }
}

// ---------------------------------------------------------------------------
// Launch. Inputs (metadata order): inputs f32 [8192*20000], weights f32 [nnz],
// bias f32 [3000], rows i32 [nnz], cols i32 [nnz]. Output f32 [8192*3000].
// ---------------------------------------------------------------------------
extern "C" void kernel_launch(void* const* d_in, const int* in_sizes, int n_in,
                              void* d_out, int out_size)
{
    const float* x    = (const float*)d_in[0];
    const float* wts  = (const float*)d_in[1];
    const float* bias = (const float*)d_in[2];
    const int*   rows = (const int*)  d_in[3];
    const int*   cols = (const int*)  d_in[4];
    const int    nnz  = in_sizes[1];
    float* out = (float*)d_out;

    build_rowptr_kernel<<<(OUT_F + 1 + 255) / 256, 256>>>(rows, nnz);
    transpose_in_kernel<<<dim3(IN_F / 32, BATCH / 64), 256>>>(x);
    spmm_kernel<<<dim3(OUT_F, BATCH / (SPMM_T * VB)), SPMM_T>>>(cols, wts);
    transpose_out_kernel<<<dim3((OUT_F + 31) / 32, BATCH / 64), 256>>>(bias, out);
}